// round 1
// baseline (speedup 1.0000x reference)
#include <cuda_runtime.h>

#define B_ 8
#define P_ 10
#define S_ 160
#define FX_ 11
#define D_ 64
#define DFF_ 256
#define NROW (B_*P_*S_)   /* 12800 */
#define NPART (B_*P_)     /* 80 */

/* output layout (tuple order): pred, pred_resampl, K, V, R, attn_weights */
#define OFF_PRED  0
#define OFF_PRED2 (NROW)
#define OFF_K     (2*NROW)
#define OFF_V     (OFF_K + NROW*D_)
#define OFF_R     (OFF_V + NROW*D_)
#define OFF_ATTN  (OFF_R + NROW*D_)

/* scratch (no cudaMalloc allowed) */
__device__ float g_x[NROW*D_];
__device__ float g_q[NROW*D_];
__device__ float g_z[NROW*D_];

/* ------------------------------------------------------------------ */
/* K1: x = (in @ Wp + bp)*8 ; Q,K,V = x @ W{q,k,v} + b.  64 rows/block */
/* ------------------------------------------------------------------ */
__global__ void __launch_bounds__(256) k_proj_qkv(
    const float* __restrict__ inp,
    const float* __restrict__ Wp, const float* __restrict__ bp,
    const float* __restrict__ Wq, const float* __restrict__ bq,
    const float* __restrict__ Wk, const float* __restrict__ bk,
    const float* __restrict__ Wv, const float* __restrict__ bv,
    float* __restrict__ outK, float* __restrict__ outV)
{
    extern __shared__ float sm[];
    float* sWp = sm;               /* 704  */
    float* sWq = sWp + 704;        /* 4096 */
    float* sWk = sWq + 4096;
    float* sWv = sWk + 4096;
    float* sB  = sWv + 4096;       /* 256  */
    float* sIn = sB + 256;         /* 704  */
    float* sX  = sIn + 704;        /* 4096 */
    const int tid = threadIdx.x;

    for (int i = tid; i < 704;  i += 256) sWp[i] = Wp[i];
    for (int i = tid; i < 4096; i += 256) { sWq[i]=Wq[i]; sWk[i]=Wk[i]; sWv[i]=Wv[i]; }
    if (tid < 64) { sB[tid]=bp[tid]; sB[64+tid]=bq[tid]; sB[128+tid]=bk[tid]; sB[192+tid]=bv[tid]; }
    const int row0 = blockIdx.x * 64;
    for (int i = tid; i < 64*11; i += 256) sIn[i] = inp[row0*11 + i];
    __syncthreads();

    const int j  = tid & 63;
    const int rb = (tid >> 6) * 16;

    /* x projection */
    {
        float acc[16];
        #pragma unroll
        for (int r = 0; r < 16; ++r) acc[r] = sB[j];
        #pragma unroll
        for (int i = 0; i < 11; ++i) {
            float wv = sWp[i*64 + j];
            #pragma unroll
            for (int r = 0; r < 16; ++r) acc[r] += sIn[(rb+r)*11 + i] * wv;
        }
        #pragma unroll
        for (int r = 0; r < 16; ++r) {
            float v = acc[r] * 8.0f;      /* * sqrt(d_model) */
            sX[(rb+r)*64 + j] = v;
            g_x[(size_t)(row0+rb+r)*64 + j] = v;
        }
    }
    __syncthreads();

    /* Q */
    {
        float acc[16];
        #pragma unroll
        for (int r = 0; r < 16; ++r) acc[r] = sB[64+j];
        #pragma unroll 4
        for (int i = 0; i < 64; ++i) {
            float wv = sWq[i*64 + j];
            #pragma unroll
            for (int r = 0; r < 16; ++r) acc[r] += sX[(rb+r)*64 + i] * wv;
        }
        #pragma unroll
        for (int r = 0; r < 16; ++r) g_q[(size_t)(row0+rb+r)*64 + j] = acc[r];
    }
    /* K */
    {
        float acc[16];
        #pragma unroll
        for (int r = 0; r < 16; ++r) acc[r] = sB[128+j];
        #pragma unroll 4
        for (int i = 0; i < 64; ++i) {
            float wv = sWk[i*64 + j];
            #pragma unroll
            for (int r = 0; r < 16; ++r) acc[r] += sX[(rb+r)*64 + i] * wv;
        }
        #pragma unroll
        for (int r = 0; r < 16; ++r) outK[(size_t)(row0+rb+r)*64 + j] = acc[r];
    }
    /* V */
    {
        float acc[16];
        #pragma unroll
        for (int r = 0; r < 16; ++r) acc[r] = sB[192+j];
        #pragma unroll 4
        for (int i = 0; i < 64; ++i) {
            float wv = sWv[i*64 + j];
            #pragma unroll
            for (int r = 0; r < 16; ++r) acc[r] += sX[(rb+r)*64 + i] * wv;
        }
        #pragma unroll
        for (int r = 0; r < 16; ++r) outV[(size_t)(row0+rb+r)*64 + j] = acc[r];
    }
}

/* ------------------------------------------------------------------ */
/* K2: causal attention per particle. 2 blocks/particle (t parity).   */
/* ------------------------------------------------------------------ */
__global__ void __launch_bounds__(256) k_attn(
    const float* __restrict__ outK, const float* __restrict__ outV,
    float* __restrict__ attnOut)
{
    extern __shared__ float sm[];
    float* sKt = sm;             /* 64 x 161 (padded transpose) = 10304 */
    float* sV  = sKt + 10304;    /* 160 x 64 = 10240 */
    float* sQ  = sV  + 10240;    /* 80 x 64  = 5120  */
    float* sA  = sQ  + 5120;     /* 8 warps x 160    */

    const int tid  = threadIdx.x;
    const int lane = tid & 31;
    const int w    = tid >> 5;
    const int part = blockIdx.x >> 1;
    const int par  = blockIdx.x & 1;

    const float* Kg = outK + (size_t)part*160*64;
    const float* Vg = outV + (size_t)part*160*64;

    for (int idx = tid; idx < 160*64; idx += 256) {
        int s = idx >> 6, i = idx & 63;
        sKt[i*161 + s] = Kg[idx];
        sV[idx]        = Vg[idx];
    }
    for (int idx = tid; idx < 80*64; idx += 256) {
        int m = idx >> 6, i = idx & 63;
        sQ[idx] = g_q[(size_t)(part*160 + par + 2*m)*64 + i];
    }
    __syncthreads();

    for (int k = 0; k < 10; ++k) {
        const int m  = w + 8*k;
        const int t  = par + 2*m;
        const int nc = (t >> 5) + 1;          /* active 32-wide chunks */
        const float* qrow = sQ + m*64;

        float sc[5] = {0.f,0.f,0.f,0.f,0.f};
        #pragma unroll 4
        for (int i = 0; i < 64; ++i) {
            float qi = qrow[i];
            const float* kr = sKt + i*161 + lane;
            #pragma unroll
            for (int c = 0; c < 5; ++c)
                if (c < nc) sc[c] += qi * kr[c*32];
        }

        /* softmax over s <= t (masked entries are exactly 0, matching -1e9 mask) */
        float mval = -3.4e38f;
        #pragma unroll
        for (int c = 0; c < 5; ++c) {
            int s = c*32 + lane;
            if (c < nc && s <= t) mval = fmaxf(mval, sc[c]*0.125f);
        }
        #pragma unroll
        for (int o = 16; o; o >>= 1) mval = fmaxf(mval, __shfl_xor_sync(0xffffffffu, mval, o));

        float p[5]; float sum = 0.f;
        #pragma unroll
        for (int c = 0; c < 5; ++c) {
            int s = c*32 + lane;
            p[c] = (c < nc && s <= t) ? expf(sc[c]*0.125f - mval) : 0.0f;
            sum += p[c];
        }
        #pragma unroll
        for (int o = 16; o; o >>= 1) sum += __shfl_xor_sync(0xffffffffu, sum, o);
        float inv = 1.0f / sum;

        float* arow = attnOut + (size_t)(part*160 + t)*160;
        float* aw   = sA + w*160;
        #pragma unroll
        for (int c = 0; c < 5; ++c) {
            float a = p[c] * inv;
            arow[c*32 + lane] = a;       /* zeros beyond t included */
            aw[c*32 + lane]   = a;
        }
        __syncwarp();

        /* z = attn @ V */
        float z0 = 0.f, z1 = 0.f;
        for (int s = 0; s <= t; ++s) {
            float a = aw[s];
            z0 += a * sV[s*64 + lane];
            z1 += a * sV[s*64 + lane + 32];
        }
        const size_t n = (size_t)part*160 + t;
        g_z[n*64 + lane]      = z0;
        g_z[n*64 + lane + 32] = z1;
    }
}

/* ------------------------------------------------------------------ */
/* K3: Wo + LN1 + FFN + LN2 + final proj.  32 rows/block.             */
/* ------------------------------------------------------------------ */
__global__ void __launch_bounds__(256) k_epi(
    const float* __restrict__ Wo, const float* __restrict__ bo,
    const float* __restrict__ ln1g, const float* __restrict__ ln1b,
    const float* __restrict__ W1, const float* __restrict__ b1,
    const float* __restrict__ W2, const float* __restrict__ b2,
    const float* __restrict__ ln2g, const float* __restrict__ ln2b,
    const float* __restrict__ Wf, const float* __restrict__ bf,
    float* __restrict__ outR, float* __restrict__ outP, float* __restrict__ outP2)
{
    extern __shared__ float sm[];
    float* sWo = sm;            /* 4096  */
    float* sW1 = sWo + 4096;    /* 16384 */
    float* sW2 = sW1 + 16384;   /* 16384 */
    float* sC  = sW2 + 16384;   /* 704: bo|b1|b2|l1g|l1b|l2g|l2b|Wf */
    float* sZ  = sC  + 704;     /* 2048 */
    float* sX  = sZ  + 2048;    /* 2048 */
    float* sO1 = sX  + 2048;    /* 2048 */
    float* sH  = sO1 + 2048;    /* 8192 */

    const int tid = threadIdx.x, lane = tid & 31, w = tid >> 5;

    for (int i = tid; i < 4096;  i += 256) sWo[i] = Wo[i];
    for (int i = tid; i < 16384; i += 256) { sW1[i] = W1[i]; sW2[i] = W2[i]; }
    if (tid < 64) {
        sC[tid]     = bo[tid];
        sC[320+tid] = b2[tid];
        sC[384+tid] = ln1g[tid];
        sC[448+tid] = ln1b[tid];
        sC[512+tid] = ln2g[tid];
        sC[576+tid] = ln2b[tid];
        sC[640+tid] = Wf[tid];
    }
    sC[64 + tid] = b1[tid];   /* 256 threads cover b1 */

    const int row0 = blockIdx.x * 32;
    for (int i = tid; i < 2048; i += 256) {
        sZ[i] = g_z[(size_t)row0*64 + i];
        sX[i] = g_x[(size_t)row0*64 + i];
    }
    __syncthreads();

    const int j  = tid & 63;
    const int rb = (tid >> 6) * 8;

    /* z @ Wo + bo + x */
    {
        float acc[8];
        #pragma unroll
        for (int r = 0; r < 8; ++r) acc[r] = sC[j];
        #pragma unroll 4
        for (int i = 0; i < 64; ++i) {
            float wv = sWo[i*64 + j];
            #pragma unroll
            for (int r = 0; r < 8; ++r) acc[r] += sZ[(rb+r)*64 + i] * wv;
        }
        #pragma unroll
        for (int r = 0; r < 8; ++r) sO1[(rb+r)*64 + j] = acc[r] + sX[(rb+r)*64 + j];
    }
    __syncthreads();

    /* LN1 (warp per row, 2 elems/lane) */
    #pragma unroll
    for (int kk = 0; kk < 4; ++kk) {
        int r = w + 8*kk;
        float v0 = sO1[r*64 + lane], v1 = sO1[r*64 + lane + 32];
        float s = v0 + v1;
        #pragma unroll
        for (int o = 16; o; o >>= 1) s += __shfl_xor_sync(0xffffffffu, s, o);
        float mu = s * (1.0f/64.0f);
        float d0 = v0 - mu, d1 = v1 - mu;
        float q = d0*d0 + d1*d1;
        #pragma unroll
        for (int o = 16; o; o >>= 1) q += __shfl_xor_sync(0xffffffffu, q, o);
        float is = rsqrtf(q * (1.0f/64.0f) + 1e-6f);
        sO1[r*64 + lane]      = sC[384+lane]    * d0 * is + sC[448+lane];
        sO1[r*64 + lane + 32] = sC[384+lane+32] * d1 * is + sC[448+lane+32];
    }
    __syncthreads();

    /* FFN layer 1: h = relu(o1 @ W1 + b1), thread = one DFF column, 32-row reg block */
    {
        const int c = tid;
        float acc[32];
        #pragma unroll
        for (int r = 0; r < 32; ++r) acc[r] = sC[64 + c];
        #pragma unroll 2
        for (int i = 0; i < 64; ++i) {
            float wv = sW1[i*256 + c];
            #pragma unroll
            for (int r = 0; r < 32; ++r) acc[r] += sO1[r*64 + i] * wv;
        }
        #pragma unroll
        for (int r = 0; r < 32; ++r) sH[r*256 + c] = fmaxf(acc[r], 0.0f);
    }
    __syncthreads();

    /* FFN layer 2 + residual */
    {
        float acc[8];
        #pragma unroll
        for (int r = 0; r < 8; ++r) acc[r] = sC[320 + j];
        #pragma unroll 4
        for (int i = 0; i < 256; ++i) {
            float wv = sW2[i*64 + j];
            #pragma unroll
            for (int r = 0; r < 8; ++r) acc[r] += sH[(rb+r)*256 + i] * wv;
        }
        #pragma unroll
        for (int r = 0; r < 8; ++r) sZ[(rb+r)*64 + j] = acc[r] + sO1[(rb+r)*64 + j];
    }
    __syncthreads();

    /* LN2 + write R + pred */
    const float bfv = bf[0];
    #pragma unroll
    for (int kk = 0; kk < 4; ++kk) {
        int r = w + 8*kk;
        float v0 = sZ[r*64 + lane], v1 = sZ[r*64 + lane + 32];
        float s = v0 + v1;
        #pragma unroll
        for (int o = 16; o; o >>= 1) s += __shfl_xor_sync(0xffffffffu, s, o);
        float mu = s * (1.0f/64.0f);
        float d0 = v0 - mu, d1 = v1 - mu;
        float q = d0*d0 + d1*d1;
        #pragma unroll
        for (int o = 16; o; o >>= 1) q += __shfl_xor_sync(0xffffffffu, q, o);
        float is = rsqrtf(q * (1.0f/64.0f) + 1e-6f);
        float r0 = sC[512+lane]    * d0 * is + sC[576+lane];
        float r1 = sC[512+lane+32] * d1 * is + sC[576+lane+32];
        const size_t n = (size_t)row0 + r;
        outR[n*64 + lane]      = r0;
        outR[n*64 + lane + 32] = r1;
        float pp = r0 * sC[640+lane] + r1 * sC[640+lane+32];
        #pragma unroll
        for (int o = 16; o; o >>= 1) pp += __shfl_xor_sync(0xffffffffu, pp, o);
        if (lane == 0) {
            float pv = pp + bfv;
            outP[n]  = pv;
            outP2[n] = pv;
        }
    }
}

/* ------------------------------------------------------------------ */
extern "C" void kernel_launch(void* const* d_in, const int* in_sizes, int n_in,
                              void* d_out, int out_size)
{
    (void)in_sizes; (void)n_in; (void)out_size;
    const float* inputs = (const float*)d_in[0];
    /* d_in[1] = targets, unused */
    const float* Wp  = (const float*)d_in[2];
    const float* bp  = (const float*)d_in[3];
    const float* Wq  = (const float*)d_in[4];
    const float* bq  = (const float*)d_in[5];
    const float* Wk  = (const float*)d_in[6];
    const float* bk  = (const float*)d_in[7];
    const float* Wv  = (const float*)d_in[8];
    const float* bv  = (const float*)d_in[9];
    const float* Wo  = (const float*)d_in[10];
    const float* bo  = (const float*)d_in[11];
    const float* l1g = (const float*)d_in[12];
    const float* l1b = (const float*)d_in[13];
    const float* W1  = (const float*)d_in[14];
    const float* b1  = (const float*)d_in[15];
    const float* W2  = (const float*)d_in[16];
    const float* b2  = (const float*)d_in[17];
    const float* l2g = (const float*)d_in[18];
    const float* l2b = (const float*)d_in[19];
    const float* Wf  = (const float*)d_in[20];
    const float* bf  = (const float*)d_in[21];
    float* out = (float*)d_out;

    const size_t sm1 = (size_t)(704 + 3*4096 + 256 + 704 + 4096) * 4;          /* ~72 KB  */
    const size_t sm2 = (size_t)(10304 + 10240 + 5120 + 1280) * 4;              /* ~108 KB */
    const size_t sm3 = (size_t)(4096 + 2*16384 + 704 + 3*2048 + 8192) * 4;     /* ~208 KB */

    cudaFuncSetAttribute(k_proj_qkv, cudaFuncAttributeMaxDynamicSharedMemorySize, (int)sm1);
    cudaFuncSetAttribute(k_attn,     cudaFuncAttributeMaxDynamicSharedMemorySize, (int)sm2);
    cudaFuncSetAttribute(k_epi,      cudaFuncAttributeMaxDynamicSharedMemorySize, (int)sm3);

    k_proj_qkv<<<NROW/64, 256, sm1>>>(inputs, Wp, bp, Wq, bq, Wk, bk, Wv, bv,
                                      out + OFF_K, out + OFF_V);
    k_attn<<<NPART*2, 256, sm2>>>(out + OFF_K, out + OFF_V, out + OFF_ATTN);
    k_epi<<<NROW/32, 256, sm3>>>(Wo, bo, l1g, l1b, W1, b1, W2, b2, l2g, l2b, Wf, bf,
                                 out + OFF_R, out + OFF_PRED, out + OFF_PRED2);
}

// round 2
// speedup vs baseline: 1.2416x; 1.2416x over previous
#include <cuda_runtime.h>

#define B_ 8
#define P_ 10
#define S_ 160
#define FX_ 11
#define D_ 64
#define DFF_ 256
#define NROW (B_*P_*S_)   /* 12800 */
#define NPART (B_*P_)     /* 80 */

/* output layout (tuple order): pred, pred_resampl, K, V, R, attn_weights */
#define OFF_PRED  0
#define OFF_PRED2 (NROW)
#define OFF_K     (2*NROW)
#define OFF_V     (OFF_K + NROW*D_)
#define OFF_R     (OFF_V + NROW*D_)
#define OFF_ATTN  (OFF_R + NROW*D_)

/* scratch (no cudaMalloc allowed) */
__device__ float g_x[NROW*D_];
__device__ float g_q[NROW*D_];
__device__ float g_z[NROW*D_];
__device__ float g_fw[4*704];   /* fused 11x64 weights: x,q,k,v */
__device__ float g_fb[4*64];    /* fused biases */

/* ------------------------------------------------------------------ */
/* K0: fold Wp into Wq/Wk/Wv.  4 blocks, one per output type.         */
/*   Wx = 8*Wp, bx = 8*bp                                             */
/*   Wq' = 8*(Wp@Wq), bq' = 8*(bp@Wq)+bq   (same for k,v)             */
/* ------------------------------------------------------------------ */
__global__ void __launch_bounds__(256) k_fold(
    const float* __restrict__ Wp, const float* __restrict__ bp,
    const float* __restrict__ Wq, const float* __restrict__ bq,
    const float* __restrict__ Wk, const float* __restrict__ bk,
    const float* __restrict__ Wv, const float* __restrict__ bv)
{
    __shared__ float sWp[704];
    __shared__ float sW[4096];
    const int b = blockIdx.x, tid = threadIdx.x;
    if (b == 0) {
        for (int i = tid; i < 704; i += 256) g_fw[i] = 8.0f * Wp[i];
        if (tid < 64) g_fb[tid] = 8.0f * bp[tid];
        return;
    }
    const float* W  = (b == 1) ? Wq : (b == 2) ? Wk : Wv;
    const float* bb = (b == 1) ? bq : (b == 2) ? bk : bv;
    for (int i = tid; i < 704;  i += 256) sWp[i] = Wp[i];
    for (int i = tid; i < 4096; i += 256) sW[i]  = W[i];
    __syncthreads();
    const int j = tid & 63, g = tid >> 6;
    for (int i = g; i < 11; i += 4) {
        float s = 0.0f;
        #pragma unroll 4
        for (int d = 0; d < 64; ++d) s += sWp[i*64 + d] * sW[d*64 + j];
        g_fw[b*704 + i*64 + j] = 8.0f * s;
    }
    if (tid < 64) {
        float s = 0.0f;
        for (int d = 0; d < 64; ++d) s += bp[d] * sW[d*64 + tid];
        g_fb[b*64 + tid] = 8.0f * s + bb[tid];
    }
}

/* ------------------------------------------------------------------ */
/* K1: x,q,k,v = in @ fused.  512 thr, 64 rows/block, weights in regs */
/* ------------------------------------------------------------------ */
__global__ void __launch_bounds__(512) k_qkv(
    const float* __restrict__ inp,
    float* __restrict__ outK, float* __restrict__ outV)
{
    extern __shared__ float sm[];
    float* sW  = sm;          /* 2816 */
    float* sB  = sW + 2816;   /* 256  */
    float* sIn = sB + 256;    /* 704  */
    const int tid = threadIdx.x;
    const int row0 = blockIdx.x * 64;

    for (int i = tid; i < 2816; i += 512) sW[i] = g_fw[i];
    if (tid < 256) sB[tid] = g_fb[tid];
    for (int i = tid; i < 704; i += 512) sIn[i] = inp[(size_t)row0*11 + i];
    __syncthreads();

    const int j = tid & 63, rb = (tid >> 6) * 8;
    float wx[11], wq[11], wk[11], wv[11];
    #pragma unroll
    for (int i = 0; i < 11; ++i) {
        wx[i] = sW[i*64 + j];
        wq[i] = sW[704  + i*64 + j];
        wk[i] = sW[1408 + i*64 + j];
        wv[i] = sW[2112 + i*64 + j];
    }
    float ax[8], aq[8], ak[8], av[8];
    #pragma unroll
    for (int r = 0; r < 8; ++r) {
        ax[r] = sB[j]; aq[r] = sB[64+j]; ak[r] = sB[128+j]; av[r] = sB[192+j];
    }
    #pragma unroll
    for (int i = 0; i < 11; ++i) {
        #pragma unroll
        for (int r = 0; r < 8; ++r) {
            float in = sIn[(rb+r)*11 + i];
            ax[r] += in * wx[i];
            aq[r] += in * wq[i];
            ak[r] += in * wk[i];
            av[r] += in * wv[i];
        }
    }
    #pragma unroll
    for (int r = 0; r < 8; ++r) {
        size_t n = (size_t)(row0 + rb + r) * 64 + j;
        g_x[n] = ax[r];
        g_q[n] = aq[r];
        outK[n] = ak[r];
        outV[n] = av[r];
    }
}

/* ------------------------------------------------------------------ */
/* K2: causal attention. 4 blocks/particle (t mod 4). 40 rows/block.  */
/* ------------------------------------------------------------------ */
__global__ void __launch_bounds__(256) k_attn(
    const float* __restrict__ Kin, const float* __restrict__ Vin,
    float* __restrict__ attnOut)
{
    extern __shared__ float sm[];
    float* sKt = sm;             /* 64 x 161 transpose = 10304 */
    float* sV  = sKt + 10304;    /* 160 x 64 = 10240 */
    float* sQ  = sV  + 10240;    /* 40 x 64  = 2560  */
    float* sA  = sQ  + 2560;     /* 8 warps x 160 = 1280 */

    const int tid  = threadIdx.x;
    const int lane = tid & 31;
    const int w    = tid >> 5;
    const int part = blockIdx.x >> 2;
    const int quad = blockIdx.x & 3;

    const float4* Kg4 = (const float4*)(Kin + (size_t)part*160*64);
    const float4* Vg4 = (const float4*)(Vin + (size_t)part*160*64);
    float4* sV4 = (float4*)sV;

    for (int idx = tid; idx < 160*16; idx += 256) {
        int s = idx >> 4, i4 = (idx & 15) * 4;
        float4 kk = Kg4[idx];
        sKt[(i4+0)*161 + s] = kk.x;
        sKt[(i4+1)*161 + s] = kk.y;
        sKt[(i4+2)*161 + s] = kk.z;
        sKt[(i4+3)*161 + s] = kk.w;
        sV4[idx] = Vg4[idx];
    }
    for (int idx = tid; idx < 40*16; idx += 256) {
        int m = idx >> 4, i4 = idx & 15;
        int row = part*160 + quad + 4*m;
        ((float4*)(sQ + m*64))[i4] = ((const float4*)(g_q + (size_t)row*64))[i4];
    }
    __syncthreads();

    for (int k = 0; k < 5; ++k) {
        const int m  = w + 8*k;
        const int t  = quad + 4*m;
        const int nc = (t >> 5) + 1;
        const float* qrow = sQ + m*64;

        float sc[5] = {0.f,0.f,0.f,0.f,0.f};
        #pragma unroll 4
        for (int i = 0; i < 64; ++i) {
            float qi = qrow[i];
            const float* kr = sKt + i*161 + lane;
            #pragma unroll
            for (int c = 0; c < 5; ++c)
                if (c < nc) sc[c] += qi * kr[c*32];
        }

        /* softmax over s <= t (masked entries exactly 0) */
        float mval = -3.4e38f;
        #pragma unroll
        for (int c = 0; c < 5; ++c) {
            int s = c*32 + lane;
            if (c < nc && s <= t) mval = fmaxf(mval, sc[c]*0.125f);
        }
        #pragma unroll
        for (int o = 16; o; o >>= 1) mval = fmaxf(mval, __shfl_xor_sync(0xffffffffu, mval, o));

        float p[5]; float sum = 0.f;
        #pragma unroll
        for (int c = 0; c < 5; ++c) {
            int s = c*32 + lane;
            p[c] = (c < nc && s <= t) ? expf(sc[c]*0.125f - mval) : 0.0f;
            sum += p[c];
        }
        #pragma unroll
        for (int o = 16; o; o >>= 1) sum += __shfl_xor_sync(0xffffffffu, sum, o);
        float inv = 1.0f / sum;

        float* arow = attnOut + (size_t)(part*160 + t)*160;
        float* aw   = sA + w*160;
        #pragma unroll
        for (int c = 0; c < 5; ++c) {
            float a = p[c] * inv;
            arow[c*32 + lane] = a;
            aw[c*32 + lane]   = a;
        }
        __syncwarp();

        /* z = attn @ V (float2 per lane: cols 2*lane, 2*lane+1) */
        const float2* sV2 = (const float2*)sV;
        float zx = 0.f, zy = 0.f;
        int s = 0;
        for (; s + 1 <= t; s += 2) {
            float a0 = aw[s], a1 = aw[s+1];
            float2 v0 = sV2[s*32 + lane];
            float2 v1 = sV2[(s+1)*32 + lane];
            zx += a0*v0.x + a1*v1.x;
            zy += a0*v0.y + a1*v1.y;
        }
        if (s <= t) {
            float a0 = aw[s];
            float2 v0 = sV2[s*32 + lane];
            zx += a0*v0.x;
            zy += a0*v0.y;
        }
        size_t n = (size_t)part*160 + t;
        ((float2*)(g_z + n*64))[lane] = make_float2(zx, zy);
    }
}

/* ------------------------------------------------------------------ */
/* K3: Wo + LN1 + FFN + LN2 + final proj.  512 thr, 64 rows/block.    */
/* ------------------------------------------------------------------ */
__global__ void __launch_bounds__(512) k_epi(
    const float* __restrict__ Wo, const float* __restrict__ bo,
    const float* __restrict__ ln1g, const float* __restrict__ ln1b,
    const float* __restrict__ W1, const float* __restrict__ b1,
    const float* __restrict__ W2, const float* __restrict__ b2,
    const float* __restrict__ ln2g, const float* __restrict__ ln2b,
    const float* __restrict__ Wf, const float* __restrict__ bf,
    float* __restrict__ outR, float* __restrict__ outP, float* __restrict__ outP2)
{
    extern __shared__ float sm[];
    float* sWo = sm;            /* 4096  */
    float* sW1 = sWo + 4096;    /* 16384 */
    float* sW2 = sW1 + 16384;   /* 16384 */
    float* sC  = sW2 + 16384;   /* 704: bo|b1|b2|l1g|l1b|l2g|l2b|Wf */
    float* sZ  = sC  + 704;     /* 4096 */
    float* sO1 = sZ  + 4096;    /* 4096 */
    float* sH  = sO1 + 4096;    /* 64 x 128 = 8192 */

    const int tid = threadIdx.x, lane = tid & 31, w = tid >> 5;

    for (int i = tid; i < 1024; i += 512) ((float4*)sWo)[i] = ((const float4*)Wo)[i];
    for (int i = tid; i < 4096; i += 512) {
        ((float4*)sW1)[i] = ((const float4*)W1)[i];
        ((float4*)sW2)[i] = ((const float4*)W2)[i];
    }
    if (tid < 64) {
        sC[tid]     = bo[tid];
        sC[320+tid] = b2[tid];
        sC[384+tid] = ln1g[tid];
        sC[448+tid] = ln1b[tid];
        sC[512+tid] = ln2g[tid];
        sC[576+tid] = ln2b[tid];
        sC[640+tid] = Wf[tid];
    }
    if (tid < 256) sC[64 + tid] = b1[tid];

    const int row0 = blockIdx.x * 64;
    for (int i = tid; i < 1024; i += 512)
        ((float4*)sZ)[i] = ((const float4*)(g_z + (size_t)row0*64))[i];
    __syncthreads();

    const int j  = tid & 63;
    const int rb = (tid >> 6) * 8;   /* 8 groups x 8 rows */

    /* z @ Wo + bo + x */
    {
        float acc[8];
        #pragma unroll
        for (int r = 0; r < 8; ++r) acc[r] = sC[j];
        #pragma unroll 4
        for (int i = 0; i < 64; ++i) {
            float wv = sWo[i*64 + j];
            #pragma unroll
            for (int r = 0; r < 8; ++r) acc[r] += sZ[(rb+r)*64 + i] * wv;
        }
        #pragma unroll
        for (int r = 0; r < 8; ++r)
            sO1[(rb+r)*64 + j] = acc[r] + g_x[(size_t)(row0+rb+r)*64 + j];
    }
    __syncthreads();

    /* LN1: 16 warps, 4 rows each */
    #pragma unroll
    for (int kk = 0; kk < 4; ++kk) {
        int r = w + 16*kk;
        float v0 = sO1[r*64 + lane], v1 = sO1[r*64 + lane + 32];
        float s = v0 + v1;
        #pragma unroll
        for (int o = 16; o; o >>= 1) s += __shfl_xor_sync(0xffffffffu, s, o);
        float mu = s * (1.0f/64.0f);
        float d0 = v0 - mu, d1 = v1 - mu;
        float q = d0*d0 + d1*d1;
        #pragma unroll
        for (int o = 16; o; o >>= 1) q += __shfl_xor_sync(0xffffffffu, q, o);
        float is = rsqrtf(q * (1.0f/64.0f) + 1e-6f);
        sO1[r*64 + lane]      = sC[384+lane]    * d0 * is + sC[448+lane];
        sO1[r*64 + lane + 32] = sC[384+lane+32] * d1 * is + sC[448+lane+32];
    }
    __syncthreads();

    /* FFN: two 128-wide halves of DFF, accumulating FFN2 across halves */
    float acc2[8];
    #pragma unroll
    for (int r = 0; r < 8; ++r) acc2[r] = sC[320 + j];

    const int c  = tid & 127;         /* FFN1 column within half */
    const int rg = (tid >> 7) * 16;   /* 4 groups x 16 rows */

    #pragma unroll
    for (int half = 0; half < 2; ++half) {
        /* FFN1 half: h = relu(o1 @ W1[:,half] + b1[half]) */
        {
            float acc[16];
            #pragma unroll
            for (int r = 0; r < 16; ++r) acc[r] = sC[64 + half*128 + c];
            #pragma unroll 2
            for (int i = 0; i < 64; ++i) {
                float wv = sW1[i*256 + half*128 + c];
                #pragma unroll
                for (int r = 0; r < 16; ++r) acc[r] += sO1[(rg+r)*64 + i] * wv;
            }
            #pragma unroll
            for (int r = 0; r < 16; ++r) sH[(rg+r)*128 + c] = fmaxf(acc[r], 0.0f);
        }
        __syncthreads();
        /* FFN2 partial */
        #pragma unroll 2
        for (int i = 0; i < 128; ++i) {
            float wv = sW2[(half*128 + i)*64 + j];
            #pragma unroll
            for (int r = 0; r < 8; ++r) acc2[r] += sH[(rb+r)*128 + i] * wv;
        }
        __syncthreads();
    }
    #pragma unroll
    for (int r = 0; r < 8; ++r) sZ[(rb+r)*64 + j] = acc2[r] + sO1[(rb+r)*64 + j];
    __syncthreads();

    /* LN2 + write R + pred */
    const float bfv = bf[0];
    #pragma unroll
    for (int kk = 0; kk < 4; ++kk) {
        int r = w + 16*kk;
        float v0 = sZ[r*64 + lane], v1 = sZ[r*64 + lane + 32];
        float s = v0 + v1;
        #pragma unroll
        for (int o = 16; o; o >>= 1) s += __shfl_xor_sync(0xffffffffu, s, o);
        float mu = s * (1.0f/64.0f);
        float d0 = v0 - mu, d1 = v1 - mu;
        float q = d0*d0 + d1*d1;
        #pragma unroll
        for (int o = 16; o; o >>= 1) q += __shfl_xor_sync(0xffffffffu, q, o);
        float is = rsqrtf(q * (1.0f/64.0f) + 1e-6f);
        float r0 = sC[512+lane]    * d0 * is + sC[576+lane];
        float r1 = sC[512+lane+32] * d1 * is + sC[576+lane+32];
        const size_t n = (size_t)row0 + r;
        outR[n*64 + lane]      = r0;
        outR[n*64 + lane + 32] = r1;
        float pp = r0 * sC[640+lane] + r1 * sC[640+lane+32];
        #pragma unroll
        for (int o = 16; o; o >>= 1) pp += __shfl_xor_sync(0xffffffffu, pp, o);
        if (lane == 0) {
            float pv = pp + bfv;
            outP[n]  = pv;
            outP2[n] = pv;
        }
    }
}

/* ------------------------------------------------------------------ */
extern "C" void kernel_launch(void* const* d_in, const int* in_sizes, int n_in,
                              void* d_out, int out_size)
{
    (void)in_sizes; (void)n_in; (void)out_size;
    const float* inputs = (const float*)d_in[0];
    /* d_in[1] = targets, unused */
    const float* Wp  = (const float*)d_in[2];
    const float* bp  = (const float*)d_in[3];
    const float* Wq  = (const float*)d_in[4];
    const float* bq  = (const float*)d_in[5];
    const float* Wk  = (const float*)d_in[6];
    const float* bk  = (const float*)d_in[7];
    const float* Wv  = (const float*)d_in[8];
    const float* bv  = (const float*)d_in[9];
    const float* Wo  = (const float*)d_in[10];
    const float* bo  = (const float*)d_in[11];
    const float* l1g = (const float*)d_in[12];
    const float* l1b = (const float*)d_in[13];
    const float* W1  = (const float*)d_in[14];
    const float* b1  = (const float*)d_in[15];
    const float* W2  = (const float*)d_in[16];
    const float* b2  = (const float*)d_in[17];
    const float* l2g = (const float*)d_in[18];
    const float* l2b = (const float*)d_in[19];
    const float* Wf  = (const float*)d_in[20];
    const float* bf  = (const float*)d_in[21];
    float* out = (float*)d_out;

    const size_t sm1 = (size_t)(2816 + 256 + 704) * 4;                          /* ~15 KB  */
    const size_t sm2 = (size_t)(10304 + 10240 + 2560 + 1280) * 4;               /* ~95 KB  */
    const size_t sm3 = (size_t)(4096 + 2*16384 + 704 + 2*4096 + 8192) * 4;      /* ~211 KB */

    cudaFuncSetAttribute(k_qkv,  cudaFuncAttributeMaxDynamicSharedMemorySize, (int)sm1);
    cudaFuncSetAttribute(k_attn, cudaFuncAttributeMaxDynamicSharedMemorySize, (int)sm2);
    cudaFuncSetAttribute(k_epi,  cudaFuncAttributeMaxDynamicSharedMemorySize, (int)sm3);

    k_fold<<<4, 256>>>(Wp, bp, Wq, bq, Wk, bk, Wv, bv);
    k_qkv<<<NROW/64, 512, sm1>>>(inputs, out + OFF_K, out + OFF_V);
    k_attn<<<NPART*4, 256, sm2>>>(out + OFF_K, out + OFF_V, out + OFF_ATTN);
    k_epi<<<NROW/64, 512, sm3>>>(Wo, bo, l1g, l1b, W1, b1, W2, b2, l2g, l2b, Wf, bf,
                                 out + OFF_R, out + OFF_PRED, out + OFF_PRED2);
}

// round 3
// speedup vs baseline: 1.4307x; 1.1523x over previous
#include <cuda_runtime.h>

#define B_ 8
#define P_ 10
#define S_ 160
#define FX_ 11
#define D_ 64
#define DFF_ 256
#define NROW (B_*P_*S_)   /* 12800 */
#define NPART (B_*P_)     /* 80 */

/* output layout (tuple order): pred, pred_resampl, K, V, R, attn_weights */
#define OFF_PRED  0
#define OFF_PRED2 (NROW)
#define OFF_K     (2*NROW)
#define OFF_V     (OFF_K + NROW*D_)
#define OFF_R     (OFF_V + NROW*D_)
#define OFF_ATTN  (OFF_R + NROW*D_)

/* scratch (no cudaMalloc allowed) */
__device__ float g_x[NROW*D_];
__device__ float g_q[NROW*D_];
__device__ float g_z[NROW*D_];
__device__ float g_fw[4*704];   /* fused 11x64 weights: x,q,k,v */
__device__ float g_fb[4*64];    /* fused biases */

/* ------------------------------------------------------------------ */
/* K0: fold Wp into Wq/Wk/Wv.                                         */
/* ------------------------------------------------------------------ */
__global__ void __launch_bounds__(256) k_fold(
    const float* __restrict__ Wp, const float* __restrict__ bp,
    const float* __restrict__ Wq, const float* __restrict__ bq,
    const float* __restrict__ Wk, const float* __restrict__ bk,
    const float* __restrict__ Wv, const float* __restrict__ bv)
{
    __shared__ float sWp[704];
    __shared__ float sW[4096];
    const int b = blockIdx.x, tid = threadIdx.x;
    if (b == 0) {
        for (int i = tid; i < 704; i += 256) g_fw[i] = 8.0f * Wp[i];
        if (tid < 64) g_fb[tid] = 8.0f * bp[tid];
        return;
    }
    const float* W  = (b == 1) ? Wq : (b == 2) ? Wk : Wv;
    const float* bb = (b == 1) ? bq : (b == 2) ? bk : bv;
    for (int i = tid; i < 704;  i += 256) sWp[i] = Wp[i];
    for (int i = tid; i < 4096; i += 256) sW[i]  = W[i];
    __syncthreads();
    const int j = tid & 63, g = tid >> 6;
    for (int i = g; i < 11; i += 4) {
        float s = 0.0f;
        #pragma unroll 4
        for (int d = 0; d < 64; ++d) s += sWp[i*64 + d] * sW[d*64 + j];
        g_fw[b*704 + i*64 + j] = 8.0f * s;
    }
    if (tid < 64) {
        float s = 0.0f;
        for (int d = 0; d < 64; ++d) s += bp[d] * sW[d*64 + tid];
        g_fb[b*64 + tid] = 8.0f * s + bb[tid];
    }
}

/* ------------------------------------------------------------------ */
/* K1: x,q,k,v = in @ fused.  512 thr, 64 rows/block, weights in regs */
/* ------------------------------------------------------------------ */
__global__ void __launch_bounds__(512) k_qkv(
    const float* __restrict__ inp,
    float* __restrict__ outK, float* __restrict__ outV)
{
    extern __shared__ float sm[];
    float* sW  = sm;          /* 2816 */
    float* sB  = sW + 2816;   /* 256  */
    float* sIn = sB + 256;    /* 704  */
    const int tid = threadIdx.x;
    const int row0 = blockIdx.x * 64;

    for (int i = tid; i < 2816; i += 512) sW[i] = g_fw[i];
    if (tid < 256) sB[tid] = g_fb[tid];
    for (int i = tid; i < 704; i += 512) sIn[i] = inp[(size_t)row0*11 + i];
    __syncthreads();

    const int j = tid & 63, rb = (tid >> 6) * 8;
    float wx[11], wq[11], wk[11], wv[11];
    #pragma unroll
    for (int i = 0; i < 11; ++i) {
        wx[i] = sW[i*64 + j];
        wq[i] = sW[704  + i*64 + j];
        wk[i] = sW[1408 + i*64 + j];
        wv[i] = sW[2112 + i*64 + j];
    }
    float ax[8], aq[8], ak[8], av[8];
    #pragma unroll
    for (int r = 0; r < 8; ++r) {
        ax[r] = sB[j]; aq[r] = sB[64+j]; ak[r] = sB[128+j]; av[r] = sB[192+j];
    }
    #pragma unroll
    for (int i = 0; i < 11; ++i) {
        #pragma unroll
        for (int r = 0; r < 8; ++r) {
            float in = sIn[(rb+r)*11 + i];
            ax[r] += in * wx[i];
            aq[r] += in * wq[i];
            ak[r] += in * wk[i];
            av[r] += in * wv[i];
        }
    }
    #pragma unroll
    for (int r = 0; r < 8; ++r) {
        size_t n = (size_t)(row0 + rb + r) * 64 + j;
        g_x[n] = ax[r];
        g_q[n] = aq[r];
        outK[n] = ak[r];
        outV[n] = av[r];
    }
}

/* ------------------------------------------------------------------ */
/* K2: causal attention. 4 blocks/particle (t mod 4). 40 rows/block.  */
/* Phase 1: scores+softmax (5 rows x 5 chunks per warp, in regs)      */
/* Phase 2: Z = A @ V register-blocked (zeros beyond t keep it exact) */
/* ------------------------------------------------------------------ */
__global__ void __launch_bounds__(256) k_attn(
    const float* __restrict__ Kin, const float* __restrict__ Vin,
    float* __restrict__ attnOut)
{
    extern __shared__ float sm[];
    float* sKt = sm;             /* 64 x 161 transpose = 10304; reused as sA (40x160) */
    float* sV  = sKt + 10304;    /* 160 x 64 = 10240 */
    float* sQ  = sV  + 10240;    /* 40 x 64  = 2560  */
    float* sA  = sKt;

    const int tid  = threadIdx.x;
    const int lane = tid & 31;
    const int w    = tid >> 5;
    const int part = blockIdx.x >> 2;
    const int quad = blockIdx.x & 3;

    const float4* Kg4 = (const float4*)(Kin + (size_t)part*160*64);
    const float4* Vg4 = (const float4*)(Vin + (size_t)part*160*64);
    float4* sV4 = (float4*)sV;

    for (int idx = tid; idx < 160*16; idx += 256) {
        int s = idx >> 4, i4 = (idx & 15) * 4;
        float4 kk = Kg4[idx];
        sKt[(i4+0)*161 + s] = kk.x;
        sKt[(i4+1)*161 + s] = kk.y;
        sKt[(i4+2)*161 + s] = kk.z;
        sKt[(i4+3)*161 + s] = kk.w;
        sV4[idx] = Vg4[idx];
    }
    for (int idx = tid; idx < 40*16; idx += 256) {
        int m = idx >> 4, i4 = idx & 15;
        int row = part*160 + quad + 4*m;
        ((float4*)(sQ + m*64))[i4] = ((const float4*)(g_q + (size_t)row*64))[i4];
    }
    __syncthreads();

    /* ---- phase 1: scores for 5 rows (m = w+8k) x 160 cols ---- */
    float sc[5][5];
    #pragma unroll
    for (int k = 0; k < 5; ++k)
        #pragma unroll
        for (int c = 0; c < 5; ++c) sc[k][c] = 0.0f;

    #pragma unroll 2
    for (int i = 0; i < 64; ++i) {
        float kv[5];
        #pragma unroll
        for (int c = 0; c < 5; ++c) kv[c] = sKt[i*161 + c*32 + lane];
        #pragma unroll
        for (int k = 0; k < 5; ++k) {
            float qi = sQ[(w + 8*k)*64 + i];
            #pragma unroll
            for (int c = 0; c < 5; ++c) sc[k][c] += qi * kv[c];
        }
    }

    /* softmax per row, masked s<=t; normalized weights kept in sc */
    #pragma unroll
    for (int k = 0; k < 5; ++k) {
        const int t = quad + 4*(w + 8*k);
        float mval = -3.4e38f;
        #pragma unroll
        for (int c = 0; c < 5; ++c) {
            int s = c*32 + lane;
            if (s <= t) mval = fmaxf(mval, sc[k][c]*0.125f);
        }
        #pragma unroll
        for (int o = 16; o; o >>= 1) mval = fmaxf(mval, __shfl_xor_sync(0xffffffffu, mval, o));
        float sum = 0.0f;
        #pragma unroll
        for (int c = 0; c < 5; ++c) {
            int s = c*32 + lane;
            float p = (s <= t) ? expf(sc[k][c]*0.125f - mval) : 0.0f;
            sc[k][c] = p;
            sum += p;
        }
        #pragma unroll
        for (int o = 16; o; o >>= 1) sum += __shfl_xor_sync(0xffffffffu, sum, o);
        float inv = 1.0f / sum;
        float* arow = attnOut + (size_t)(part*160 + t)*160;
        #pragma unroll
        for (int c = 0; c < 5; ++c) {
            sc[k][c] *= inv;
            arow[c*32 + lane] = sc[k][c];
        }
    }

    __syncthreads();   /* everyone done reading sKt */

    /* stage A into smem (overwrites sKt) */
    #pragma unroll
    for (int k = 0; k < 5; ++k) {
        const int m = w + 8*k;
        #pragma unroll
        for (int c = 0; c < 5; ++c) sA[m*160 + c*32 + lane] = sc[k][c];
    }
    __syncwarp();

    /* ---- phase 2: Z = A @ V, 5 rows x 2 cols per thread ---- */
    const float2* sV2 = (const float2*)sV;
    float2 acc[5];
    #pragma unroll
    for (int k = 0; k < 5; ++k) acc[k] = make_float2(0.f, 0.f);

    for (int s = 0; s < 160; s += 4) {
        float4 a[5];
        #pragma unroll
        for (int k = 0; k < 5; ++k)
            a[k] = *(const float4*)(sA + (w + 8*k)*160 + s);
        float2 v0 = sV2[(s+0)*32 + lane];
        float2 v1 = sV2[(s+1)*32 + lane];
        float2 v2 = sV2[(s+2)*32 + lane];
        float2 v3 = sV2[(s+3)*32 + lane];
        #pragma unroll
        for (int k = 0; k < 5; ++k) {
            acc[k].x += a[k].x*v0.x + a[k].y*v1.x + a[k].z*v2.x + a[k].w*v3.x;
            acc[k].y += a[k].x*v0.y + a[k].y*v1.y + a[k].z*v2.y + a[k].w*v3.y;
        }
    }
    #pragma unroll
    for (int k = 0; k < 5; ++k) {
        const int t = quad + 4*(w + 8*k);
        size_t n = (size_t)part*160 + t;
        ((float2*)(g_z + n*64))[lane] = acc[k];
    }
}

/* ------------------------------------------------------------------ */
/* K3: persistent 148-block epilogue. 16-row tiles, 800 tiles.        */
/* ------------------------------------------------------------------ */
__global__ void __launch_bounds__(512) k_epi(
    const float* __restrict__ Wo, const float* __restrict__ bo,
    const float* __restrict__ ln1g, const float* __restrict__ ln1b,
    const float* __restrict__ W1, const float* __restrict__ b1,
    const float* __restrict__ W2, const float* __restrict__ b2,
    const float* __restrict__ ln2g, const float* __restrict__ ln2b,
    const float* __restrict__ Wf, const float* __restrict__ bf,
    float* __restrict__ outR, float* __restrict__ outP, float* __restrict__ outP2)
{
    extern __shared__ float sm[];
    float* sWo = sm;            /* 4096  */
    float* sW1 = sWo + 4096;    /* 16384 */
    float* sW2 = sW1 + 16384;   /* 16384 */
    float* sC  = sW2 + 16384;   /* 704: bo|b1|b2|l1g|l1b|l2g|l2b|Wf */
    float* sZ  = sC  + 704;     /* 16 x 64 = 1024 */
    float* sO1 = sZ  + 1024;    /* 1024 */
    float* sH  = sO1 + 1024;    /* 16 x 256 = 4096 */

    const int tid = threadIdx.x, lane = tid & 31, w = tid >> 5;

    for (int i = tid; i < 1024; i += 512) ((float4*)sWo)[i] = ((const float4*)Wo)[i];
    for (int i = tid; i < 4096; i += 512) {
        ((float4*)sW1)[i] = ((const float4*)W1)[i];
        ((float4*)sW2)[i] = ((const float4*)W2)[i];
    }
    if (tid < 64) {
        sC[tid]     = bo[tid];
        sC[320+tid] = b2[tid];
        sC[384+tid] = ln1g[tid];
        sC[448+tid] = ln1b[tid];
        sC[512+tid] = ln2g[tid];
        sC[576+tid] = ln2b[tid];
        sC[640+tid] = Wf[tid];
    }
    if (tid < 256) sC[64 + tid] = b1[tid];
    const float bfv = bf[0];
    __syncthreads();

    const int rp  = tid >> 6;        /* FFN1 row-pair 0..7 */
    const int c4  = tid & 63;        /* FFN1 col-quad      */

    for (int tile = blockIdx.x; tile < NROW/16; tile += gridDim.x) {
        const int row0 = tile * 16;

        /* stage tile z */
        ((float2*)sZ)[tid] = ((const float2*)(g_z + (size_t)row0*64))[tid];
        __syncthreads();

        /* ---- Wo: out = z @ Wo + bo + x ;  1 row x 2 cols per thread ---- */
        {
            float2 resid = ((const float2*)(g_x + (size_t)(row0 + w)*64))[lane];
            float2 acc = make_float2(sC[2*lane], sC[2*lane+1]);
            #pragma unroll 8
            for (int i = 0; i < 64; ++i) {
                float z = sZ[w*64 + i];
                float2 wv = ((const float2*)(sWo + i*64))[lane];
                acc.x += z * wv.x;
                acc.y += z * wv.y;
            }
            sO1[w*64 + 2*lane]   = acc.x + resid.x;
            sO1[w*64 + 2*lane+1] = acc.y + resid.y;
        }
        __syncwarp();

        /* ---- LN1: warp w handles row w ---- */
        {
            float v0 = sO1[w*64 + lane], v1 = sO1[w*64 + lane + 32];
            float s = v0 + v1;
            #pragma unroll
            for (int o = 16; o; o >>= 1) s += __shfl_xor_sync(0xffffffffu, s, o);
            float mu = s * (1.0f/64.0f);
            float d0 = v0 - mu, d1 = v1 - mu;
            float q = d0*d0 + d1*d1;
            #pragma unroll
            for (int o = 16; o; o >>= 1) q += __shfl_xor_sync(0xffffffffu, q, o);
            float is = rsqrtf(q * (1.0f/64.0f) + 1e-6f);
            sO1[w*64 + lane]      = sC[384+lane]    * d0 * is + sC[448+lane];
            sO1[w*64 + lane + 32] = sC[384+lane+32] * d1 * is + sC[448+lane+32];
        }
        __syncthreads();

        /* ---- FFN1: h = relu(o1 @ W1 + b1); 2 rows x 4 cols per thread ---- */
        {
            float4 b = ((const float4*)(sC + 64))[c4];
            float4 a0 = b, a1 = b;
            #pragma unroll 4
            for (int i = 0; i < 64; ++i) {
                float4 wv = ((const float4*)(sW1 + i*256))[c4];
                float x0 = sO1[(2*rp)*64 + i];
                float x1 = sO1[(2*rp+1)*64 + i];
                a0.x += x0*wv.x; a0.y += x0*wv.y; a0.z += x0*wv.z; a0.w += x0*wv.w;
                a1.x += x1*wv.x; a1.y += x1*wv.y; a1.z += x1*wv.z; a1.w += x1*wv.w;
            }
            a0.x = fmaxf(a0.x, 0.f); a0.y = fmaxf(a0.y, 0.f);
            a0.z = fmaxf(a0.z, 0.f); a0.w = fmaxf(a0.w, 0.f);
            a1.x = fmaxf(a1.x, 0.f); a1.y = fmaxf(a1.y, 0.f);
            a1.z = fmaxf(a1.z, 0.f); a1.w = fmaxf(a1.w, 0.f);
            ((float4*)(sH + (2*rp)*256))[c4]   = a0;
            ((float4*)(sH + (2*rp+1)*256))[c4] = a1;
        }
        __syncthreads();

        /* ---- FFN2 + residual: 1 row x 2 cols per thread ---- */
        {
            float2 acc = make_float2(sC[320 + 2*lane], sC[320 + 2*lane + 1]);
            #pragma unroll 8
            for (int i = 0; i < 256; ++i) {
                float a = sH[w*256 + i];
                float2 wv = ((const float2*)(sW2 + i*64))[lane];
                acc.x += a * wv.x;
                acc.y += a * wv.y;
            }
            sZ[w*64 + 2*lane]   = acc.x + sO1[w*64 + 2*lane];
            sZ[w*64 + 2*lane+1] = acc.y + sO1[w*64 + 2*lane+1];
        }
        __syncwarp();

        /* ---- LN2 + R + pred: warp w handles row w ---- */
        {
            float v0 = sZ[w*64 + lane], v1 = sZ[w*64 + lane + 32];
            float s = v0 + v1;
            #pragma unroll
            for (int o = 16; o; o >>= 1) s += __shfl_xor_sync(0xffffffffu, s, o);
            float mu = s * (1.0f/64.0f);
            float d0 = v0 - mu, d1 = v1 - mu;
            float q = d0*d0 + d1*d1;
            #pragma unroll
            for (int o = 16; o; o >>= 1) q += __shfl_xor_sync(0xffffffffu, q, o);
            float is = rsqrtf(q * (1.0f/64.0f) + 1e-6f);
            float r0 = sC[512+lane]    * d0 * is + sC[576+lane];
            float r1 = sC[512+lane+32] * d1 * is + sC[576+lane+32];
            const size_t n = (size_t)row0 + w;
            outR[n*64 + lane]      = r0;
            outR[n*64 + lane + 32] = r1;
            float pp = r0 * sC[640+lane] + r1 * sC[640+lane+32];
            #pragma unroll
            for (int o = 16; o; o >>= 1) pp += __shfl_xor_sync(0xffffffffu, pp, o);
            if (lane == 0) {
                float pv = pp + bfv;
                outP[n]  = pv;
                outP2[n] = pv;
            }
        }
        __syncthreads();
    }
}

/* ------------------------------------------------------------------ */
extern "C" void kernel_launch(void* const* d_in, const int* in_sizes, int n_in,
                              void* d_out, int out_size)
{
    (void)in_sizes; (void)n_in; (void)out_size;
    const float* inputs = (const float*)d_in[0];
    const float* Wp  = (const float*)d_in[2];
    const float* bp  = (const float*)d_in[3];
    const float* Wq  = (const float*)d_in[4];
    const float* bq  = (const float*)d_in[5];
    const float* Wk  = (const float*)d_in[6];
    const float* bk  = (const float*)d_in[7];
    const float* Wv  = (const float*)d_in[8];
    const float* bv  = (const float*)d_in[9];
    const float* Wo  = (const float*)d_in[10];
    const float* bo  = (const float*)d_in[11];
    const float* l1g = (const float*)d_in[12];
    const float* l1b = (const float*)d_in[13];
    const float* W1  = (const float*)d_in[14];
    const float* b1  = (const float*)d_in[15];
    const float* W2  = (const float*)d_in[16];
    const float* b2  = (const float*)d_in[17];
    const float* l2g = (const float*)d_in[18];
    const float* l2b = (const float*)d_in[19];
    const float* Wf  = (const float*)d_in[20];
    const float* bf  = (const float*)d_in[21];
    float* out = (float*)d_out;

    const size_t sm1 = (size_t)(2816 + 256 + 704) * 4;                        /* ~15 KB  */
    const size_t sm2 = (size_t)(10304 + 10240 + 2560) * 4;                    /* ~92 KB  */
    const size_t sm3 = (size_t)(4096 + 2*16384 + 704 + 2*1024 + 4096) * 4;    /* ~175 KB */

    cudaFuncSetAttribute(k_qkv,  cudaFuncAttributeMaxDynamicSharedMemorySize, (int)sm1);
    cudaFuncSetAttribute(k_attn, cudaFuncAttributeMaxDynamicSharedMemorySize, (int)sm2);
    cudaFuncSetAttribute(k_epi,  cudaFuncAttributeMaxDynamicSharedMemorySize, (int)sm3);

    k_fold<<<4, 256>>>(Wp, bp, Wq, bq, Wk, bk, Wv, bv);
    k_qkv<<<NROW/64, 512, sm1>>>(inputs, out + OFF_K, out + OFF_V);
    k_attn<<<NPART*4, 256, sm2>>>(out + OFF_K, out + OFF_V, out + OFF_ATTN);
    k_epi<<<148, 512, sm3>>>(Wo, bo, l1g, l1b, W1, b1, W2, b2, l2g, l2b, Wf, bf,
                             out + OFF_R, out + OFF_PRED, out + OFF_PRED2);
}

// round 5
// speedup vs baseline: 1.8641x; 1.3029x over previous
#include <cuda_runtime.h>

#define B_ 8
#define P_ 10
#define S_ 160
#define FX_ 11
#define D_ 64
#define DFF_ 256
#define NROW (B_*P_*S_)   /* 12800 */
#define NPART (B_*P_)     /* 80 */

/* output layout (tuple order): pred, pred_resampl, K, V, R, attn_weights */
#define OFF_PRED  0
#define OFF_PRED2 (NROW)
#define OFF_K     (2*NROW)
#define OFF_V     (OFF_K + NROW*D_)
#define OFF_R     (OFF_V + NROW*D_)
#define OFF_ATTN  (OFF_R + NROW*D_)

/* scratch (no cudaMalloc allowed) */
__device__ float g_x[NROW*D_];
__device__ float g_q[NROW*D_];
__device__ float g_z[NROW*D_];
__device__ float g_fw[4*704];   /* fused 11x64 weights: x,q,k,v */
__device__ float g_fb[4*64];    /* fused biases */

__device__ __forceinline__ void fma4(float4& acc, float s, const float4& v) {
    acc.x += s * v.x; acc.y += s * v.y; acc.z += s * v.z; acc.w += s * v.w;
}

/* ------------------------------------------------------------------ */
/* K0: fold Wp into Wq/Wk/Wv. Attention scale 1/8 folded into Wq.     */
/* ------------------------------------------------------------------ */
__global__ void __launch_bounds__(256) k_fold(
    const float* __restrict__ Wp, const float* __restrict__ bp,
    const float* __restrict__ Wq, const float* __restrict__ bq,
    const float* __restrict__ Wk, const float* __restrict__ bk,
    const float* __restrict__ Wv, const float* __restrict__ bv)
{
    __shared__ float sWp[704];
    __shared__ float sW[4096];
    const int b = blockIdx.x, tid = threadIdx.x;
    if (b == 0) {
        for (int i = tid; i < 704; i += 256) g_fw[i] = 8.0f * Wp[i];
        if (tid < 64) g_fb[tid] = 8.0f * bp[tid];
        return;
    }
    const float* W  = (b == 1) ? Wq : (b == 2) ? Wk : Wv;
    const float* bb = (b == 1) ? bq : (b == 2) ? bk : bv;
    const float fw = (b == 1) ? 1.0f   : 8.0f;   /* 8 * (1/8 attn scale) for q */
    const float fb = (b == 1) ? 0.125f : 1.0f;
    for (int i = tid; i < 704;  i += 256) sWp[i] = Wp[i];
    for (int i = tid; i < 4096; i += 256) sW[i]  = W[i];
    __syncthreads();
    const int j = tid & 63, g = tid >> 6;
    for (int i = g; i < 11; i += 4) {
        float s = 0.0f;
        #pragma unroll 4
        for (int d = 0; d < 64; ++d) s += sWp[i*64 + d] * sW[d*64 + j];
        g_fw[b*704 + i*64 + j] = fw * s;
    }
    if (tid < 64) {
        float s = 0.0f;
        for (int d = 0; d < 64; ++d) s += bp[d] * sW[d*64 + tid];
        g_fb[b*64 + tid] = fw * s + fb * bb[tid];
    }
}

/* ------------------------------------------------------------------ */
/* K1: x,q,k,v = in @ fused.  512 thr, 64 rows/block, weights in regs */
/* ------------------------------------------------------------------ */
__global__ void __launch_bounds__(512) k_qkv(
    const float* __restrict__ inp,
    float* __restrict__ outK, float* __restrict__ outV)
{
    extern __shared__ float sm[];
    float* sW  = sm;          /* 2816 */
    float* sB  = sW + 2816;   /* 256  */
    float* sIn = sB + 256;    /* 704  */
    const int tid = threadIdx.x;
    const int row0 = blockIdx.x * 64;

    for (int i = tid; i < 2816; i += 512) sW[i] = g_fw[i];
    if (tid < 256) sB[tid] = g_fb[tid];
    for (int i = tid; i < 704; i += 512) sIn[i] = inp[(size_t)row0*11 + i];
    __syncthreads();

    const int j = tid & 63, rb = (tid >> 6) * 8;
    float wx[11], wq[11], wk[11], wv[11];
    #pragma unroll
    for (int i = 0; i < 11; ++i) {
        wx[i] = sW[i*64 + j];
        wq[i] = sW[704  + i*64 + j];
        wk[i] = sW[1408 + i*64 + j];
        wv[i] = sW[2112 + i*64 + j];
    }
    float ax[8], aq[8], ak[8], av[8];
    #pragma unroll
    for (int r = 0; r < 8; ++r) {
        ax[r] = sB[j]; aq[r] = sB[64+j]; ak[r] = sB[128+j]; av[r] = sB[192+j];
    }
    #pragma unroll
    for (int i = 0; i < 11; ++i) {
        #pragma unroll
        for (int r = 0; r < 8; ++r) {
            float in = sIn[(rb+r)*11 + i];
            ax[r] += in * wx[i];
            aq[r] += in * wq[i];
            ak[r] += in * wk[i];
            av[r] += in * wv[i];
        }
    }
    #pragma unroll
    for (int r = 0; r < 8; ++r) {
        size_t n = (size_t)(row0 + rb + r) * 64 + j;
        g_x[n] = ax[r];
        g_q[n] = aq[r];
        outK[n] = ak[r];
        outV[n] = av[r];
    }
}

/* ------------------------------------------------------------------ */
/* K2: causal attention. 4 blocks/particle. q pre-scaled by 1/8.      */
/* ------------------------------------------------------------------ */
__global__ void __launch_bounds__(256) k_attn(
    const float* __restrict__ Kin, const float* __restrict__ Vin,
    float* __restrict__ attnOut)
{
    extern __shared__ float sm[];
    float* sKt = sm;             /* 64 x 161 = 10304; reused as sA (40x160) */
    float* sV  = sKt + 10304;    /* 160 x 64 = 10240 */
    float* sQ  = sV  + 10240;    /* 40 x 64  = 2560  */
    float* sA  = sKt;

    const int tid  = threadIdx.x;
    const int lane = tid & 31;
    const int w    = tid >> 5;
    const int part = blockIdx.x >> 2;
    const int quad = blockIdx.x & 3;

    const float4* Kg4 = (const float4*)(Kin + (size_t)part*160*64);
    const float4* Vg4 = (const float4*)(Vin + (size_t)part*160*64);
    float4* sV4 = (float4*)sV;

    for (int idx = tid; idx < 160*16; idx += 256) {
        int s = idx >> 4, i4 = (idx & 15) * 4;
        float4 kk = Kg4[idx];
        sKt[(i4+0)*161 + s] = kk.x;
        sKt[(i4+1)*161 + s] = kk.y;
        sKt[(i4+2)*161 + s] = kk.z;
        sKt[(i4+3)*161 + s] = kk.w;
        sV4[idx] = Vg4[idx];
    }
    for (int idx = tid; idx < 40*16; idx += 256) {
        int m = idx >> 4, i4 = idx & 15;
        int row = part*160 + quad + 4*m;
        ((float4*)(sQ + m*64))[i4] = ((const float4*)(g_q + (size_t)row*64))[i4];
    }
    __syncthreads();

    /* phase 1: scores for 5 rows x 160 cols */
    float sc[5][5];
    #pragma unroll
    for (int k = 0; k < 5; ++k)
        #pragma unroll
        for (int c = 0; c < 5; ++c) sc[k][c] = 0.0f;

    #pragma unroll 2
    for (int i = 0; i < 64; ++i) {
        float kv[5];
        #pragma unroll
        for (int c = 0; c < 5; ++c) kv[c] = sKt[i*161 + c*32 + lane];
        #pragma unroll
        for (int k = 0; k < 5; ++k) {
            float qi = sQ[(w + 8*k)*64 + i];
            #pragma unroll
            for (int c = 0; c < 5; ++c) sc[k][c] += qi * kv[c];
        }
    }

    #pragma unroll
    for (int k = 0; k < 5; ++k) {
        const int t = quad + 4*(w + 8*k);
        float mval = -3.4e38f;
        #pragma unroll
        for (int c = 0; c < 5; ++c) {
            int s = c*32 + lane;
            if (s <= t) mval = fmaxf(mval, sc[k][c]);
        }
        #pragma unroll
        for (int o = 16; o; o >>= 1) mval = fmaxf(mval, __shfl_xor_sync(0xffffffffu, mval, o));
        float sum = 0.0f;
        #pragma unroll
        for (int c = 0; c < 5; ++c) {
            int s = c*32 + lane;
            float p = (s <= t) ? expf(sc[k][c] - mval) : 0.0f;
            sc[k][c] = p;
            sum += p;
        }
        #pragma unroll
        for (int o = 16; o; o >>= 1) sum += __shfl_xor_sync(0xffffffffu, sum, o);
        float inv = 1.0f / sum;
        float* arow = attnOut + (size_t)(part*160 + t)*160;
        #pragma unroll
        for (int c = 0; c < 5; ++c) {
            sc[k][c] *= inv;
            arow[c*32 + lane] = sc[k][c];
        }
    }

    __syncthreads();

    #pragma unroll
    for (int k = 0; k < 5; ++k) {
        const int m = w + 8*k;
        #pragma unroll
        for (int c = 0; c < 5; ++c) sA[m*160 + c*32 + lane] = sc[k][c];
    }
    __syncwarp();

    /* phase 2: Z = A @ V, 5 rows x 2 cols per thread */
    const float2* sV2 = (const float2*)sV;
    float2 acc[5];
    #pragma unroll
    for (int k = 0; k < 5; ++k) acc[k] = make_float2(0.f, 0.f);

    for (int s = 0; s < 160; s += 4) {
        float4 a[5];
        #pragma unroll
        for (int k = 0; k < 5; ++k)
            a[k] = *(const float4*)(sA + (w + 8*k)*160 + s);
        float2 v0 = sV2[(s+0)*32 + lane];
        float2 v1 = sV2[(s+1)*32 + lane];
        float2 v2 = sV2[(s+2)*32 + lane];
        float2 v3 = sV2[(s+3)*32 + lane];
        #pragma unroll
        for (int k = 0; k < 5; ++k) {
            acc[k].x += a[k].x*v0.x + a[k].y*v1.x + a[k].z*v2.x + a[k].w*v3.x;
            acc[k].y += a[k].x*v0.y + a[k].y*v1.y + a[k].z*v2.y + a[k].w*v3.y;
        }
    }
    #pragma unroll
    for (int k = 0; k < 5; ++k) {
        const int t = quad + 4*(w + 8*k);
        size_t n = (size_t)part*160 + t;
        ((float2*)(g_z + n*64))[lane] = acc[k];
    }
}

/* ------------------------------------------------------------------ */
/* K3: persistent epilogue, 32-row tiles, 4x4 register-block GEMMs.   */
/* ------------------------------------------------------------------ */
__global__ void __launch_bounds__(512) k_epi(
    const float* __restrict__ Wo, const float* __restrict__ bo,
    const float* __restrict__ ln1g, const float* __restrict__ ln1b,
    const float* __restrict__ W1, const float* __restrict__ b1,
    const float* __restrict__ W2, const float* __restrict__ b2,
    const float* __restrict__ ln2g, const float* __restrict__ ln2b,
    const float* __restrict__ Wf, const float* __restrict__ bf,
    float* __restrict__ outR, float* __restrict__ outP, float* __restrict__ outP2)
{
    extern __shared__ float sm[];
    float* sWo = sm;            /* 4096  */
    float* sW1 = sWo + 4096;    /* 16384 */
    float* sW2 = sW1 + 16384;   /* 16384 */
    float* sC  = sW2 + 16384;   /* 704: bo|b1|b2|l1g|l1b|l2g|l2b|Wf */
    float* sO1 = sC  + 704;     /* 32 x 64 = 2048 */
    float* sH  = sO1 + 2048;    /* 32 x 256 = 8192 (also Wo partials 4x2048) */
    float* sP  = sH  + 8192;    /* 4096: FFN2 partials 2x2048, then pre-LN2 */

    const int tid = threadIdx.x, lane = tid & 31, w = tid >> 5;

    for (int i = tid; i < 1024; i += 512) ((float4*)sWo)[i] = ((const float4*)Wo)[i];
    for (int i = tid; i < 4096; i += 512) {
        ((float4*)sW1)[i] = ((const float4*)W1)[i];
        ((float4*)sW2)[i] = ((const float4*)W2)[i];
    }
    if (tid < 64) {
        sC[tid]     = bo[tid];
        sC[320+tid] = b2[tid];
        sC[384+tid] = ln1g[tid];
        sC[448+tid] = ln1b[tid];
        sC[512+tid] = ln2g[tid];
        sC[576+tid] = ln2b[tid];
        sC[640+tid] = Wf[tid];
    }
    if (tid < 256) sC[64 + tid] = b1[tid];
    const float bfv = bf[0];
    __syncthreads();

    for (int tile = blockIdx.x; tile < NROW/32; tile += gridDim.x) {
        const int row0 = tile * 32;

        /* ---- Wo: 4-way K-split (16 i each), 16cq x 8rq, 4 rows x 4 cols ---- */
        {
            const int isp = tid >> 7;           /* 0..3 */
            const int t1  = tid & 127;
            const int cq  = t1 & 15;
            const int rq  = t1 >> 4;            /* 0..7 */
            float4 acc0 = {0,0,0,0}, acc1 = {0,0,0,0}, acc2 = {0,0,0,0}, acc3 = {0,0,0,0};
            #pragma unroll
            for (int i4 = isp*4; i4 < isp*4 + 4; ++i4) {
                float4 w0 = ((const float4*)(sWo + (i4*4+0)*64))[cq];
                float4 w1 = ((const float4*)(sWo + (i4*4+1)*64))[cq];
                float4 w2 = ((const float4*)(sWo + (i4*4+2)*64))[cq];
                float4 w3 = ((const float4*)(sWo + (i4*4+3)*64))[cq];
                float4 a0 = ((const float4*)(g_z + (size_t)(row0 + 4*rq+0)*64))[i4];
                float4 a1 = ((const float4*)(g_z + (size_t)(row0 + 4*rq+1)*64))[i4];
                float4 a2 = ((const float4*)(g_z + (size_t)(row0 + 4*rq+2)*64))[i4];
                float4 a3 = ((const float4*)(g_z + (size_t)(row0 + 4*rq+3)*64))[i4];
                fma4(acc0, a0.x, w0); fma4(acc0, a0.y, w1); fma4(acc0, a0.z, w2); fma4(acc0, a0.w, w3);
                fma4(acc1, a1.x, w0); fma4(acc1, a1.y, w1); fma4(acc1, a1.z, w2); fma4(acc1, a1.w, w3);
                fma4(acc2, a2.x, w0); fma4(acc2, a2.y, w1); fma4(acc2, a2.z, w2); fma4(acc2, a2.w, w3);
                fma4(acc3, a3.x, w0); fma4(acc3, a3.y, w1); fma4(acc3, a3.z, w2); fma4(acc3, a3.w, w3);
            }
            float4* dst = (float4*)(sH + isp*2048);
            dst[(4*rq+0)*16 + cq] = acc0;
            dst[(4*rq+1)*16 + cq] = acc1;
            dst[(4*rq+2)*16 + cq] = acc2;
            dst[(4*rq+3)*16 + cq] = acc3;
        }
        __syncthreads();
        /* reduce + bias + residual -> sO1 */
        {
            const float4* p = (const float4*)sH;
            float4 v = p[tid];
            float4 v1 = p[512 + tid], v2 = p[1024 + tid], v3 = p[1536 + tid];
            v.x += v1.x + v2.x + v3.x;
            v.y += v1.y + v2.y + v3.y;
            v.z += v1.z + v2.z + v3.z;
            v.w += v1.w + v2.w + v3.w;
            const int row = tid >> 4, c4 = tid & 15;
            float4 b = ((const float4*)sC)[c4];
            float4 rx = ((const float4*)(g_x + (size_t)(row0 + row)*64))[c4];
            v.x += b.x + rx.x; v.y += b.y + rx.y; v.z += b.z + rx.z; v.w += b.w + rx.w;
            ((float4*)sO1)[tid] = v;
        }
        __syncthreads();

        /* ---- LN1: 16 warps x 2 rows ---- */
        #pragma unroll
        for (int kk = 0; kk < 2; ++kk) {
            int r = w + 16*kk;
            float v0 = sO1[r*64 + lane], v1 = sO1[r*64 + lane + 32];
            float s = v0 + v1;
            #pragma unroll
            for (int o = 16; o; o >>= 1) s += __shfl_xor_sync(0xffffffffu, s, o);
            float mu = s * (1.0f/64.0f);
            float d0 = v0 - mu, d1 = v1 - mu;
            float q = d0*d0 + d1*d1;
            #pragma unroll
            for (int o = 16; o; o >>= 1) q += __shfl_xor_sync(0xffffffffu, q, o);
            float is = rsqrtf(q * (1.0f/64.0f) + 1e-6f);
            sO1[r*64 + lane]      = sC[384+lane]    * d0 * is + sC[448+lane];
            sO1[r*64 + lane + 32] = sC[384+lane+32] * d1 * is + sC[448+lane+32];
        }
        __syncthreads();

        /* ---- FFN1: 64cq x 8rq, 4 rows x 4 cols, relu ---- */
        {
            const int cq = tid & 63;
            const int rq = tid >> 6;
            float4 b = ((const float4*)(sC + 64))[cq];
            float4 acc0 = b, acc1 = b, acc2 = b, acc3 = b;
            #pragma unroll 4
            for (int i4 = 0; i4 < 16; ++i4) {
                float4 w0 = ((const float4*)(sW1 + (i4*4+0)*256))[cq];
                float4 w1 = ((const float4*)(sW1 + (i4*4+1)*256))[cq];
                float4 w2 = ((const float4*)(sW1 + (i4*4+2)*256))[cq];
                float4 w3 = ((const float4*)(sW1 + (i4*4+3)*256))[cq];
                float4 a0 = ((const float4*)(sO1 + (4*rq+0)*64))[i4];
                float4 a1 = ((const float4*)(sO1 + (4*rq+1)*64))[i4];
                float4 a2 = ((const float4*)(sO1 + (4*rq+2)*64))[i4];
                float4 a3 = ((const float4*)(sO1 + (4*rq+3)*64))[i4];
                fma4(acc0, a0.x, w0); fma4(acc0, a0.y, w1); fma4(acc0, a0.z, w2); fma4(acc0, a0.w, w3);
                fma4(acc1, a1.x, w0); fma4(acc1, a1.y, w1); fma4(acc1, a1.z, w2); fma4(acc1, a1.w, w3);
                fma4(acc2, a2.x, w0); fma4(acc2, a2.y, w1); fma4(acc2, a2.z, w2); fma4(acc2, a2.w, w3);
                fma4(acc3, a3.x, w0); fma4(acc3, a3.y, w1); fma4(acc3, a3.z, w2); fma4(acc3, a3.w, w3);
            }
            acc0.x = fmaxf(acc0.x, 0.f); acc0.y = fmaxf(acc0.y, 0.f);
            acc0.z = fmaxf(acc0.z, 0.f); acc0.w = fmaxf(acc0.w, 0.f);
            acc1.x = fmaxf(acc1.x, 0.f); acc1.y = fmaxf(acc1.y, 0.f);
            acc1.z = fmaxf(acc1.z, 0.f); acc1.w = fmaxf(acc1.w, 0.f);
            acc2.x = fmaxf(acc2.x, 0.f); acc2.y = fmaxf(acc2.y, 0.f);
            acc2.z = fmaxf(acc2.z, 0.f); acc2.w = fmaxf(acc2.w, 0.f);
            acc3.x = fmaxf(acc3.x, 0.f); acc3.y = fmaxf(acc3.y, 0.f);
            acc3.z = fmaxf(acc3.z, 0.f); acc3.w = fmaxf(acc3.w, 0.f);
            ((float4*)(sH + (4*rq+0)*256))[cq] = acc0;
            ((float4*)(sH + (4*rq+1)*256))[cq] = acc1;
            ((float4*)(sH + (4*rq+2)*256))[cq] = acc2;
            ((float4*)(sH + (4*rq+3)*256))[cq] = acc3;
        }
        __syncthreads();

        /* ---- FFN2: 2-way K-split (128 i each), 16cq x 16rq, 2 rows x 4 cols ---- */
        {
            const int isp = tid >> 8;           /* 0..1 */
            const int t2  = tid & 255;
            const int cq  = t2 & 15;
            const int rq  = t2 >> 4;            /* 0..15 */
            float4 acc0 = {0,0,0,0}, acc1 = {0,0,0,0};
            #pragma unroll 4
            for (int i4 = isp*32; i4 < isp*32 + 32; ++i4) {
                float4 w0 = ((const float4*)(sW2 + (i4*4+0)*64))[cq];
                float4 w1 = ((const float4*)(sW2 + (i4*4+1)*64))[cq];
                float4 w2 = ((const float4*)(sW2 + (i4*4+2)*64))[cq];
                float4 w3 = ((const float4*)(sW2 + (i4*4+3)*64))[cq];
                float4 a0 = ((const float4*)(sH + (2*rq+0)*256))[i4];
                float4 a1 = ((const float4*)(sH + (2*rq+1)*256))[i4];
                fma4(acc0, a0.x, w0); fma4(acc0, a0.y, w1); fma4(acc0, a0.z, w2); fma4(acc0, a0.w, w3);
                fma4(acc1, a1.x, w0); fma4(acc1, a1.y, w1); fma4(acc1, a1.z, w2); fma4(acc1, a1.w, w3);
            }
            float4* dst = (float4*)(sP + isp*2048);
            dst[(2*rq+0)*16 + cq] = acc0;
            dst[(2*rq+1)*16 + cq] = acc1;
        }
        __syncthreads();
        /* reduce + bias + residual -> sP[0..2047] (pre-LN2) */
        {
            const float4* p = (const float4*)sP;
            float4 v = p[tid];
            float4 v1 = p[512 + tid];
            const int row = tid >> 4, c4 = tid & 15;
            float4 b = ((const float4*)(sC + 320))[c4];
            float4 rs = ((const float4*)(sO1 + row*64))[c4];
            v.x += v1.x + b.x + rs.x;
            v.y += v1.y + b.y + rs.y;
            v.z += v1.z + b.z + rs.z;
            v.w += v1.w + b.w + rs.w;
            ((float4*)sP)[tid] = v;
        }
        __syncthreads();

        /* ---- LN2 + R + pred: 16 warps x 2 rows ---- */
        #pragma unroll
        for (int kk = 0; kk < 2; ++kk) {
            int r = w + 16*kk;
            float v0 = sP[r*64 + lane], v1 = sP[r*64 + lane + 32];
            float s = v0 + v1;
            #pragma unroll
            for (int o = 16; o; o >>= 1) s += __shfl_xor_sync(0xffffffffu, s, o);
            float mu = s * (1.0f/64.0f);
            float d0 = v0 - mu, d1 = v1 - mu;
            float q = d0*d0 + d1*d1;
            #pragma unroll
            for (int o = 16; o; o >>= 1) q += __shfl_xor_sync(0xffffffffu, q, o);
            float is = rsqrtf(q * (1.0f/64.0f) + 1e-6f);
            float r0 = sC[512+lane]    * d0 * is + sC[576+lane];
            float r1 = sC[512+lane+32] * d1 * is + sC[576+lane+32];
            const size_t n = (size_t)row0 + r;
            outR[n*64 + lane]      = r0;
            outR[n*64 + lane + 32] = r1;
            float pp = r0 * sC[640+lane] + r1 * sC[640+lane+32];
            #pragma unroll
            for (int o = 16; o; o >>= 1) pp += __shfl_xor_sync(0xffffffffu, pp, o);
            if (lane == 0) {
                float pv = pp + bfv;
                outP[n]  = pv;
                outP2[n] = pv;
            }
        }
        __syncthreads();
    }
}

/* ------------------------------------------------------------------ */
extern "C" void kernel_launch(void* const* d_in, const int* in_sizes, int n_in,
                              void* d_out, int out_size)
{
    (void)in_sizes; (void)n_in; (void)out_size;
    const float* inputs = (const float*)d_in[0];
    const float* Wp  = (const float*)d_in[2];
    const float* bp  = (const float*)d_in[3];
    const float* Wq  = (const float*)d_in[4];
    const float* bq  = (const float*)d_in[5];
    const float* Wk  = (const float*)d_in[6];
    const float* bk  = (const float*)d_in[7];
    const float* Wv  = (const float*)d_in[8];
    const float* bv  = (const float*)d_in[9];
    const float* Wo  = (const float*)d_in[10];
    const float* bo  = (const float*)d_in[11];
    const float* l1g = (const float*)d_in[12];
    const float* l1b = (const float*)d_in[13];
    const float* W1  = (const float*)d_in[14];
    const float* b1  = (const float*)d_in[15];
    const float* W2  = (const float*)d_in[16];
    const float* b2  = (const float*)d_in[17];
    const float* l2g = (const float*)d_in[18];
    const float* l2b = (const float*)d_in[19];
    const float* Wf  = (const float*)d_in[20];
    const float* bf  = (const float*)d_in[21];
    float* out = (float*)d_out;

    const size_t sm1 = (size_t)(2816 + 256 + 704) * 4;                          /* ~15 KB  */
    const size_t sm2 = (size_t)(10304 + 10240 + 2560) * 4;                      /* ~92 KB  */
    const size_t sm3 = (size_t)(4096 + 16384 + 16384 + 704 + 2048 + 8192 + 4096) * 4; /* ~203 KB */

    cudaFuncSetAttribute(k_qkv,  cudaFuncAttributeMaxDynamicSharedMemorySize, (int)sm1);
    cudaFuncSetAttribute(k_attn, cudaFuncAttributeMaxDynamicSharedMemorySize, (int)sm2);
    cudaFuncSetAttribute(k_epi,  cudaFuncAttributeMaxDynamicSharedMemorySize, (int)sm3);

    k_fold<<<4, 256>>>(Wp, bp, Wq, bq, Wk, bk, Wv, bv);
    k_qkv<<<NROW/64, 512, sm1>>>(inputs, out + OFF_K, out + OFF_V);
    k_attn<<<NPART*4, 256, sm2>>>(out + OFF_K, out + OFF_V, out + OFF_ATTN);
    k_epi<<<148, 512, sm3>>>(Wo, bo, l1g, l1b, W1, b1, W2, b2, l2g, l2b, Wf, bf,
                             out + OFF_R, out + OFF_PRED, out + OFF_PRED2);
}